// round 1
// baseline (speedup 1.0000x reference)
#include <cuda_runtime.h>
#include <cstdint>
#include <cstddef>

// ---------------------------------------------------------------------------
// SNN forward:
//   cur1 = data @ w1^T + b1                      (once; data time-invariant)
//   spk1_t computed elementwise from cur1 (beta1=1.0) -> bit-packed uint8
//   cur2[t] = spk1_t @ w2^T + b2  -> one GEMM with M = T*B, A from bits
//   fused: mem2/spk2 recurrence + dot(w3) + mean  -> out[B]
// ---------------------------------------------------------------------------

static constexpr int T_STEPS = 8;
static constexpr int B_MAXC  = 16384;
static constexpr int H0_MAXC = 1024;
static constexpr int H1_MAXC = 512;

// Scratch (device globals -- no runtime allocation allowed)
__device__ float         g_cur1[(size_t)B_MAXC * H0_MAXC];                  // 64 MB
__device__ unsigned char g_pack[(size_t)B_MAXC * H0_MAXC];                  // 16 MB
__device__ float         g_cur2[(size_t)T_STEPS * B_MAXC * H1_MAXC];        // 256 MB

// ---------------------------------------------------------------------------
// SGEMM (NT): C[m,n] = sum_k A[m,k] * W[n,k] + bias[n]
// MODE 0: A is a dense float matrix (lda = K)
// MODE 1: A[m,k] = bit t of pack[b*K + k], where m = t*batchB + b  (binary)
// Tile 128x128x16, 256 threads, 8x8 per-thread micro-tile.
// ---------------------------------------------------------------------------
template <int MODE>
__global__ void __launch_bounds__(256) sgemm_nt_kernel(
    const float* __restrict__ A,
    const unsigned char* __restrict__ pack,
    const float* __restrict__ W,
    const float* __restrict__ bias,
    float* __restrict__ C,
    int M, int N, int K, int batchB)
{
    __shared__ float As[16][128];
    __shared__ float Bs[16][128];

    const int tx = threadIdx.x;
    const int tm = tx >> 4;    // 0..15
    const int tn = tx & 15;    // 0..15

    const int m0 = blockIdx.y * 128;
    const int n0 = blockIdx.x * 128;

    float acc[8][8];
#pragma unroll
    for (int i = 0; i < 8; ++i)
#pragma unroll
        for (int j = 0; j < 8; ++j) acc[i][j] = 0.0f;

    for (int kt = 0; kt < K; kt += 16) {
        // ---- load A tile (128 rows x 16 k) and W tile, transposed into smem
#pragma unroll
        for (int s = 0; s < 2; ++s) {
            const int f  = tx + s * 256;     // float4 id 0..511
            const int r  = f >> 2;           // tile row 0..127
            const int c4 = (f & 3) * 4;      // k offset within tile
            const int gk = kt + c4;

            // A side
            {
                const int gm = m0 + r;
                float4 v;
                if (MODE == 0) {
                    v = *reinterpret_cast<const float4*>(&A[(size_t)gm * K + gk]);
                } else {
                    const int t = gm / batchB;
                    const int b = gm - t * batchB;
                    const uchar4 p = *reinterpret_cast<const uchar4*>(
                        &pack[(size_t)b * K + gk]);
                    v.x = (float)((p.x >> t) & 1);
                    v.y = (float)((p.y >> t) & 1);
                    v.z = (float)((p.z >> t) & 1);
                    v.w = (float)((p.w >> t) & 1);
                }
                As[c4 + 0][r] = v.x;
                As[c4 + 1][r] = v.y;
                As[c4 + 2][r] = v.z;
                As[c4 + 3][r] = v.w;
            }
            // W side
            {
                const int gn = n0 + r;
                const float4 w = *reinterpret_cast<const float4*>(
                    &W[(size_t)gn * K + gk]);
                Bs[c4 + 0][r] = w.x;
                Bs[c4 + 1][r] = w.y;
                Bs[c4 + 2][r] = w.z;
                Bs[c4 + 3][r] = w.w;
            }
        }
        __syncthreads();

#pragma unroll
        for (int k = 0; k < 16; ++k) {
            float a[8], b[8];
            *reinterpret_cast<float4*>(&a[0]) =
                *reinterpret_cast<const float4*>(&As[k][tm * 8]);
            *reinterpret_cast<float4*>(&a[4]) =
                *reinterpret_cast<const float4*>(&As[k][tm * 8 + 4]);
            *reinterpret_cast<float4*>(&b[0]) =
                *reinterpret_cast<const float4*>(&Bs[k][tn * 8]);
            *reinterpret_cast<float4*>(&b[4]) =
                *reinterpret_cast<const float4*>(&Bs[k][tn * 8 + 4]);
#pragma unroll
            for (int i = 0; i < 8; ++i)
#pragma unroll
                for (int j = 0; j < 8; ++j)
                    acc[i][j] = fmaf(a[i], b[j], acc[i][j]);
        }
        __syncthreads();
    }

    // ---- epilogue: add bias, store
    float bj[8];
    const int gn0 = n0 + tn * 8;
#pragma unroll
    for (int j = 0; j < 8; ++j) bj[j] = __ldg(&bias[gn0 + j]);

#pragma unroll
    for (int i = 0; i < 8; ++i) {
        const int gm = m0 + tm * 8 + i;
        float4 o0, o1;
        o0.x = acc[i][0] + bj[0];
        o0.y = acc[i][1] + bj[1];
        o0.z = acc[i][2] + bj[2];
        o0.w = acc[i][3] + bj[3];
        o1.x = acc[i][4] + bj[4];
        o1.y = acc[i][5] + bj[5];
        o1.z = acc[i][6] + bj[6];
        o1.w = acc[i][7] + bj[7];
        *reinterpret_cast<float4*>(&C[(size_t)gm * N + gn0])     = o0;
        *reinterpret_cast<float4*>(&C[(size_t)gm * N + gn0 + 4]) = o1;
    }
}

// ---------------------------------------------------------------------------
// Elementwise LIF layer 1: mem1 recurrence (beta1 = 1.0), bit-pack 8 spikes.
// snntorch semantics: reset detected on OLD mem (strict >), subtract reset,
// then spike = (mem_new - 1 > 0).
// ---------------------------------------------------------------------------
__global__ void spike_pack_kernel(const float* __restrict__ cur1,
                                  unsigned char* __restrict__ pack,
                                  size_t n)
{
    size_t i = (size_t)blockIdx.x * blockDim.x + threadIdx.x;
    if (i >= n) return;
    const float c = cur1[i];
    float mem = 0.0f;
    unsigned p = 0;
#pragma unroll
    for (int t = 0; t < T_STEPS; ++t) {
        const float reset = (mem > 1.0f) ? 1.0f : 0.0f;   // OLD mem
        mem = mem + c - reset;                             // beta1 = 1.0
        p |= ((mem - 1.0f) > 0.0f ? 1u : 0u) << t;
    }
    pack[i] = (unsigned char)p;
}

// ---------------------------------------------------------------------------
// Fused layer-2 LIF + output head:
// one block per batch row; thread j owns mem2[j]; loop over t; dot with w3;
// block-reduce; out[b] = sum / T + b3.
// ---------------------------------------------------------------------------
__global__ void fuse_out_kernel(const float* __restrict__ cur2,
                                const float* __restrict__ w3,
                                const float* __restrict__ b3,
                                float* __restrict__ out,
                                int Bb, int H1)
{
    const int b = blockIdx.x;
    const int j = threadIdx.x;   // H1 threads

    const float w = __ldg(&w3[j]);
    float mem = 0.0f;
    float acc = 0.0f;
#pragma unroll
    for (int t = 0; t < T_STEPS; ++t) {
        const float c = cur2[((size_t)t * Bb + b) * H1 + j];
        const float reset = (mem > 1.0f) ? 1.0f : 0.0f;    // OLD mem
        mem = 0.95f * mem + c - reset;                     // beta2 = 0.95
        acc += ((mem - 1.0f) > 0.0f) ? w : 0.0f;
    }

    __shared__ float red[512];
    red[j] = acc;
    __syncthreads();
#pragma unroll
    for (int s = 256; s > 0; s >>= 1) {
        if (j < s) red[j] += red[j + s];
        __syncthreads();
    }
    if (j == 0) out[b] = red[0] * (1.0f / T_STEPS) + __ldg(&b3[0]);
}

// ---------------------------------------------------------------------------
extern "C" void kernel_launch(void* const* d_in, const int* in_sizes, int n_in,
                              void* d_out, int out_size)
{
    const float* data = (const float*)d_in[0];
    const float* w1   = (const float*)d_in[1];
    const float* b1   = (const float*)d_in[2];
    const float* w2   = (const float*)d_in[3];
    const float* b2   = (const float*)d_in[4];
    const float* w3   = (const float*)d_in[5];
    const float* b3   = (const float*)d_in[6];
    // d_in[7] = time_steps (always 8 per setup_inputs; T_STEPS compile-time)

    const int H0 = in_sizes[2];                 // 1024
    const int D  = in_sizes[1] / H0;            // 512
    const int Bb = in_sizes[0] / D;             // 16384
    const int H1 = in_sizes[4];                 // 512

    float* cur1 = nullptr;
    float* cur2 = nullptr;
    unsigned char* pack = nullptr;
    cudaGetSymbolAddress((void**)&cur1, g_cur1);
    cudaGetSymbolAddress((void**)&cur2, g_cur2);
    cudaGetSymbolAddress((void**)&pack, g_pack);

    float* out = (float*)d_out;

    // 1) GEMM1: cur1[B, H0] = data @ w1^T + b1
    {
        dim3 grid(H0 / 128, Bb / 128);
        sgemm_nt_kernel<0><<<grid, 256>>>(data, nullptr, w1, b1, cur1,
                                          Bb, H0, D, Bb);
    }

    // 2) spike pack: 8 steps of spk1 -> uint8 bits
    {
        const size_t n = (size_t)Bb * H0;
        const int threads = 256;
        const int blocks = (int)((n + threads - 1) / threads);
        spike_pack_kernel<<<blocks, threads>>>(cur1, pack, n);
    }

    // 3) GEMM2 (batched over t): cur2[T*B, H1] = spk1 @ w2^T + b2
    {
        const int M2 = T_STEPS * Bb;
        dim3 grid(H1 / 128, M2 / 128);
        sgemm_nt_kernel<1><<<grid, 256>>>(nullptr, pack, w2, b2, cur2,
                                          M2, H1, H0, Bb);
    }

    // 4) fused LIF2 + output head
    {
        fuse_out_kernel<<<Bb, H1>>>(cur2, w3, b3, out, Bb, H1);
    }
}

// round 5
// speedup vs baseline: 1.0276x; 1.0276x over previous
#include <cuda_runtime.h>
#include <cstdint>
#include <cstddef>

// ---------------------------------------------------------------------------
// SNN forward:
//   cur1 = data @ w1^T + b1        -- fp32 SIMT GEMM (round-1 verbatim: known
//                                     numerics, cur1 bit-identical to round 1)
//   spk1 (s8 0/1) [T*B, H0]        -- elementwise LIF1 (beta1 = 1.0)
//   w2 -> 3 signed-byte limbs (24-bit fixed point, scale 2^-27)
//   cur2 = spk1 @ w2^T + b2        -- int8 tensor-core GEMM, EXACT integer
//                                     accumulation per limb + fp32 combine
//   fuse_out: LIF2 + dot(w3) + mean
//
// Rationale: legacy-HMMA fp32 accumulate truncates intermediate adds ->
// coherent ~2e-6 bias -> spike cascade blew rel_err to 1e-2 in rounds 3/4.
// Integer MMA has no rounding at all; quantization error is 3.7e-9/weight.
// ---------------------------------------------------------------------------

static constexpr int BB  = 16384;
static constexpr int DIN = 512;
static constexpr int H0  = 1024;
static constexpr int H1  = 512;
static constexpr int T   = 8;
static constexpr int M2  = T * BB;

// Scratch (device globals -- no runtime allocation allowed)
__device__ __align__(256) int8_t g_spk[(size_t)M2 * H0];        // 128 MB
__device__ __align__(256) int8_t g_q2 [(size_t)H1 * 3 * H0];    // 1.5 MB
__device__ __align__(256) float  g_cur1[(size_t)BB * H0];       //  64 MB
__device__ __align__(256) float  g_cur2[(size_t)M2 * H1];       // 256 MB

// ---------------------------------------------------------------------------
// PTX helpers (sm_80+ subset, valid on compute_103)
// ---------------------------------------------------------------------------
__device__ __forceinline__ uint32_t smem_u32(const void* p) {
    uint32_t a;
    asm("{ .reg .u64 t; cvta.to.shared.u64 t, %1; cvt.u32.u64 %0, t; }"
        : "=r"(a) : "l"(p));
    return a;
}
__device__ __forceinline__ void cp16(uint32_t dst, const void* src) {
    asm volatile("cp.async.cg.shared.global [%0], [%1], 16;"
                 :: "r"(dst), "l"(src));
}
#define CP_COMMIT() asm volatile("cp.async.commit_group;" ::: "memory")
#define CP_WAIT(n)  asm volatile("cp.async.wait_group %0;" :: "n"(n) : "memory")

#define LDSM4(r0, r1, r2, r3, addr) \
    asm volatile("ldmatrix.sync.aligned.m8n8.x4.shared.b16 {%0,%1,%2,%3}, [%4];" \
        : "=r"(r0), "=r"(r1), "=r"(r2), "=r"(r3) : "r"(addr) : "memory")

// s8 x s8 -> s32, K = 32. Integer accumulate: EXACT.
#define MMA_S8(d, a, b0, b1) \
    asm volatile("mma.sync.aligned.m16n8k32.row.col.s32.s8.s8.s32 " \
        "{%0,%1,%2,%3}, {%4,%5,%6,%7}, {%8,%9}, {%0,%1,%2,%3};" \
        : "+r"((d)[0]), "+r"((d)[1]), "+r"((d)[2]), "+r"((d)[3]) \
        : "r"((a)[0]), "r"((a)[1]), "r"((a)[2]), "r"((a)[3]), \
          "r"(b0), "r"(b1))

// ===========================================================================
// GEMM1: round-1 fp32 SIMT SGEMM (verbatim numerics -- passed at 3.0e-4).
// C[m,n] = sum_k A[m,k] * W[n,k] + bias[n].  Tile 128x128x16, 8x8 micro.
// ===========================================================================
__global__ void __launch_bounds__(256) sgemm1_kernel(
    const float* __restrict__ A,
    const float* __restrict__ W,
    const float* __restrict__ bias,
    float* __restrict__ C,
    int M, int N, int K)
{
    __shared__ float As[16][128];
    __shared__ float Bs[16][128];

    const int tx = threadIdx.x;
    const int tm = tx >> 4;
    const int tn = tx & 15;

    const int m0 = blockIdx.y * 128;
    const int n0 = blockIdx.x * 128;

    float acc[8][8];
#pragma unroll
    for (int i = 0; i < 8; ++i)
#pragma unroll
        for (int j = 0; j < 8; ++j) acc[i][j] = 0.0f;

    for (int kt = 0; kt < K; kt += 16) {
#pragma unroll
        for (int s = 0; s < 2; ++s) {
            const int f  = tx + s * 256;
            const int r  = f >> 2;
            const int c4 = (f & 3) * 4;
            const int gk = kt + c4;
            {
                const int gm = m0 + r;
                float4 v = *reinterpret_cast<const float4*>(&A[(size_t)gm * K + gk]);
                As[c4 + 0][r] = v.x;
                As[c4 + 1][r] = v.y;
                As[c4 + 2][r] = v.z;
                As[c4 + 3][r] = v.w;
            }
            {
                const int gn = n0 + r;
                const float4 w = *reinterpret_cast<const float4*>(&W[(size_t)gn * K + gk]);
                Bs[c4 + 0][r] = w.x;
                Bs[c4 + 1][r] = w.y;
                Bs[c4 + 2][r] = w.z;
                Bs[c4 + 3][r] = w.w;
            }
        }
        __syncthreads();

#pragma unroll
        for (int k = 0; k < 16; ++k) {
            float a[8], b[8];
            *reinterpret_cast<float4*>(&a[0]) =
                *reinterpret_cast<const float4*>(&As[k][tm * 8]);
            *reinterpret_cast<float4*>(&a[4]) =
                *reinterpret_cast<const float4*>(&As[k][tm * 8 + 4]);
            *reinterpret_cast<float4*>(&b[0]) =
                *reinterpret_cast<const float4*>(&Bs[k][tn * 8]);
            *reinterpret_cast<float4*>(&b[4]) =
                *reinterpret_cast<const float4*>(&Bs[k][tn * 8 + 4]);
#pragma unroll
            for (int i = 0; i < 8; ++i)
#pragma unroll
                for (int j = 0; j < 8; ++j)
                    acc[i][j] = fmaf(a[i], b[j], acc[i][j]);
        }
        __syncthreads();
    }

    float bj[8];
    const int gn0 = n0 + tn * 8;
#pragma unroll
    for (int j = 0; j < 8; ++j) bj[j] = __ldg(&bias[gn0 + j]);

#pragma unroll
    for (int i = 0; i < 8; ++i) {
        const int gm = m0 + tm * 8 + i;
        float4 o0, o1;
        o0.x = acc[i][0] + bj[0];
        o0.y = acc[i][1] + bj[1];
        o0.z = acc[i][2] + bj[2];
        o0.w = acc[i][3] + bj[3];
        o1.x = acc[i][4] + bj[4];
        o1.y = acc[i][5] + bj[5];
        o1.z = acc[i][6] + bj[6];
        o1.w = acc[i][7] + bj[7];
        *reinterpret_cast<float4*>(&C[(size_t)gm * N + gn0])     = o0;
        *reinterpret_cast<float4*>(&C[(size_t)gm * N + gn0 + 4]) = o1;
    }
}

// ===========================================================================
// LIF layer 1 (beta1 = 1.0): spikes for 8 steps as s8 0/1
// ===========================================================================
__global__ void spike_expand_s8(const float* __restrict__ cur1,
                                int8_t* __restrict__ spk)
{
    const size_t i = (size_t)blockIdx.x * blockDim.x + threadIdx.x;
    if (i >= (size_t)BB * H0) return;
    const float c = cur1[i];
    float mem = 0.0f;
#pragma unroll
    for (int t = 0; t < T; ++t) {
        const float reset = (mem > 1.0f) ? 1.0f : 0.0f;   // OLD mem
        mem = mem + c - reset;
        spk[(size_t)t * BB * H0 + i] = ((mem - 1.0f) > 0.0f) ? 1 : 0;
    }
}

// ===========================================================================
// Quantize w2 to 3 signed-byte limbs: w ~= (hi*2^16 + mid*2^8 + lo) * 2^-27
// |w| < 0.0442 -> |w*2^27| < 5.94e6 -> |hi| <= 91.  Quant err <= 2^-28.
// Layout: q[n, 0:H0]=hi, [H0:2H0]=mid, [2H0:3H0]=lo
// ===========================================================================
__global__ void quant_w2_kernel(const float* __restrict__ w2,
                                int8_t* __restrict__ q)
{
    const int i = blockIdx.x * blockDim.x + threadIdx.x;
    if (i >= H1 * H0) return;
    const int n = i / H0, k = i - n * H0;
    int v = __float2int_rn(w2[i] * 134217728.0f);     // * 2^27
    const int lo  = ((v + 128) & 255) - 128;  v = (v - lo) >> 8;
    const int mid = ((v + 128) & 255) - 128;  v = (v - mid) >> 8;
    const size_t base = (size_t)n * 3 * H0 + k;
    q[base]          = (int8_t)v;     // hi
    q[base + H0]     = (int8_t)mid;
    q[base + 2 * H0] = (int8_t)lo;
}

// ===========================================================================
// GEMM2: cur2[T*B, H1] = spk @ w2^T + b2 via s8 MMA.
// CTA tile 128x64, 8 warps (4 x 2), warp tile 32x32, m16n8k32.
// 5-stage cp.async pipeline; 96 k-chunks = 3 limbs x 32 chunks of k=32.
// Per-limb s32 accumulation is exact; one weighted fp32 drain per limb.
// SMEM rows padded to 48 B -> conflict-free ldmatrix.
// ===========================================================================
static constexpr int G2_STAGES  = 5;
static constexpr int G2_A_BYTES = 128 * 48;                 // 6144
static constexpr int G2_B_BYTES = 64 * 48;                  // 3072
static constexpr int G2_STAGE   = G2_A_BYTES + G2_B_BYTES;  // 9216
static constexpr int G2_SMEM    = G2_STAGES * G2_STAGE;     // 46080

__device__ __forceinline__ void g2_load(
    const int8_t* __restrict__ A, const int8_t* __restrict__ B,
    int m0, int n0, int tid, uint32_t sbase, int it, int s)
{
    const int limb = it >> 5, kc = it & 31;
    const int aoff = kc * 32;
    const int boff = limb * H0 + kc * 32;
    const uint32_t st = sbase + s * G2_STAGE;
    const int r = tid >> 1, h = (tid & 1) * 16;
    cp16(st + r * 48 + h, A + (size_t)(m0 + r) * H0 + aoff + h);
    if (tid < 128) {
        cp16(st + G2_A_BYTES + r * 48 + h,
             B + (size_t)(n0 + r) * (3 * H0) + boff + h);
    }
}

__global__ void __launch_bounds__(256) gemm2_s8_kernel(
    const int8_t* __restrict__ A,
    const int8_t* __restrict__ B,
    const float* __restrict__ bias,
    float* __restrict__ C)
{
    extern __shared__ char smem[];
    const uint32_t sbase = smem_u32(smem);

    const int tid  = threadIdx.x;
    const int lane = tid & 31;
    const int wid  = tid >> 5;
    const int wm   = wid & 3;     // 4 warps along M (32 rows)
    const int wn   = wid >> 2;    // 2 warps along N (32 cols)
    const int m0   = blockIdx.y * 128;
    const int n0   = blockIdx.x * 64;

    float master[2][4][4];
    int   ch[2][4][4];
#pragma unroll
    for (int i = 0; i < 2; ++i)
#pragma unroll
        for (int j = 0; j < 4; ++j)
#pragma unroll
            for (int k = 0; k < 4; ++k) master[i][j][k] = 0.0f;

    // prologue
#pragma unroll
    for (int s = 0; s < G2_STAGES - 1; ++s) {
        g2_load(A, B, m0, n0, tid, sbase, s, s);
        CP_COMMIT();
    }

    // ldmatrix per-lane offsets (bytes)
    const int a_row = lane & 15;
    const int a_kb  = (lane >> 4) * 16;
    const int b_row = (lane & 7) + ((lane >> 4) * 8);
    const int b_kb  = ((lane >> 3) & 1) * 16;

    for (int it = 0; it < 96; ++it) {
        CP_WAIT(3);
        __syncthreads();

        const int nx = it + G2_STAGES - 1;
        if (nx < 96)
            g2_load(A, B, m0, n0, tid, sbase, nx, nx % G2_STAGES);
        CP_COMMIT();

        const uint32_t sa = sbase + (it % G2_STAGES) * G2_STAGE;
        const uint32_t sb = sa + G2_A_BYTES;

        uint32_t a[2][4], b[2][4];
#pragma unroll
        for (int mt = 0; mt < 2; ++mt) {
            const uint32_t ad = sa + (wm * 32 + mt * 16 + a_row) * 48 + a_kb;
            LDSM4(a[mt][0], a[mt][1], a[mt][2], a[mt][3], ad);
        }
#pragma unroll
        for (int g = 0; g < 2; ++g) {
            const uint32_t bd = sb + (wn * 32 + g * 16 + b_row) * 48 + b_kb;
            LDSM4(b[g][0], b[g][1], b[g][2], b[g][3], bd);
        }

        if ((it & 31) == 0) {   // new limb: restart exact integer chain
#pragma unroll
            for (int i = 0; i < 2; ++i)
#pragma unroll
                for (int j = 0; j < 4; ++j)
#pragma unroll
                    for (int k = 0; k < 4; ++k) ch[i][j][k] = 0;
        }

#pragma unroll
        for (int mt = 0; mt < 2; ++mt)
#pragma unroll
            for (int nt = 0; nt < 4; ++nt)
                MMA_S8(ch[mt][nt], a[mt],
                       b[nt >> 1][(nt & 1) * 2], b[nt >> 1][(nt & 1) * 2 + 1]);

        if ((it & 31) == 31) {  // end of limb: weighted fp32 drain (RN)
            const float wgt = (it == 31) ? 0x1p-11f
                            : (it == 63) ? 0x1p-19f
                                         : 0x1p-27f;
#pragma unroll
            for (int i = 0; i < 2; ++i)
#pragma unroll
                for (int j = 0; j < 4; ++j)
#pragma unroll
                    for (int k = 0; k < 4; ++k)
                        master[i][j][k] = fmaf(wgt, (float)ch[i][j][k],
                                               master[i][j][k]);
        }
    }

    // epilogue: stage through smem, coalesced vectorized store with bias
    __syncthreads();
    float* stg = (float*)smem;   // 128 x 68
#pragma unroll
    for (int mt = 0; mt < 2; ++mt)
#pragma unroll
        for (int nt = 0; nt < 4; ++nt) {
            const int r = wm * 32 + mt * 16 + (lane >> 2);
            const int c = wn * 32 + nt * 8 + (lane & 3) * 2;
            stg[(size_t)r * 68 + c]           = master[mt][nt][0];
            stg[(size_t)r * 68 + c + 1]       = master[mt][nt][1];
            stg[(size_t)(r + 8) * 68 + c]     = master[mt][nt][2];
            stg[(size_t)(r + 8) * 68 + c + 1] = master[mt][nt][3];
        }
    __syncthreads();

    const int c4 = (tid & 15) * 4;
    const int rbase = tid >> 4;
    float4 bv = *reinterpret_cast<const float4*>(bias + n0 + c4);
#pragma unroll
    for (int rr = 0; rr < 8; ++rr) {
        const int r = rbase + rr * 16;
        float4 v = *reinterpret_cast<const float4*>(stg + (size_t)r * 68 + c4);
        v.x += bv.x; v.y += bv.y; v.z += bv.z; v.w += bv.w;
        *reinterpret_cast<float4*>(&C[(size_t)(m0 + r) * H1 + n0 + c4]) = v;
    }
}

// ===========================================================================
// Fused layer-2 LIF + output head
// ===========================================================================
__global__ void fuse_out_kernel(const float* __restrict__ cur2,
                                const float* __restrict__ w3,
                                const float* __restrict__ b3,
                                float* __restrict__ out)
{
    const int b = blockIdx.x;
    const int j = threadIdx.x;

    const float w = __ldg(&w3[j]);
    float mem = 0.0f;
    float acc = 0.0f;
#pragma unroll
    for (int t = 0; t < T; ++t) {
        const float c = cur2[((size_t)t * BB + b) * H1 + j];
        const float reset = (mem > 1.0f) ? 1.0f : 0.0f;    // OLD mem
        mem = 0.95f * mem + c - reset;
        acc += ((mem - 1.0f) > 0.0f) ? w : 0.0f;
    }

    __shared__ float red[H1];
    red[j] = acc;
    __syncthreads();
#pragma unroll
    for (int s = H1 / 2; s > 0; s >>= 1) {
        if (j < s) red[j] += red[j + s];
        __syncthreads();
    }
    if (j == 0) out[b] = red[0] * (1.0f / T) + __ldg(&b3[0]);
}

// ---------------------------------------------------------------------------
extern "C" void kernel_launch(void* const* d_in, const int* in_sizes, int n_in,
                              void* d_out, int out_size)
{
    const float* data = (const float*)d_in[0];
    const float* w1   = (const float*)d_in[1];
    const float* b1   = (const float*)d_in[2];
    const float* w2   = (const float*)d_in[3];
    const float* b2   = (const float*)d_in[4];
    const float* w3   = (const float*)d_in[5];
    const float* b3   = (const float*)d_in[6];
    float* out = (float*)d_out;

    int8_t *spk, *q2;
    float *cur1, *cur2;
    cudaGetSymbolAddress((void**)&spk,  g_spk);
    cudaGetSymbolAddress((void**)&q2,   g_q2);
    cudaGetSymbolAddress((void**)&cur1, g_cur1);
    cudaGetSymbolAddress((void**)&cur2, g_cur2);

    cudaFuncSetAttribute(gemm2_s8_kernel,
                         cudaFuncAttributeMaxDynamicSharedMemorySize, G2_SMEM);

    // 1) GEMM1 (fp32 SIMT, round-1 verbatim): cur1 = data @ w1^T + b1
    {
        dim3 grid(H0 / 128, BB / 128);   // (8, 128)
        sgemm1_kernel<<<grid, 256>>>(data, w1, b1, cur1, BB, H0, DIN);
    }

    // 2) quantize w2 into 3 s8 limbs
    {
        const int n = H1 * H0;
        quant_w2_kernel<<<(n + 255) / 256, 256>>>(w2, q2);
    }

    // 3) LIF1 spikes (s8)
    {
        const size_t n = (size_t)BB * H0;
        spike_expand_s8<<<(unsigned)((n + 255) / 256), 256>>>(cur1, spk);
    }

    // 4) GEMM2 (s8 tensor cores, exact): cur2 = spk @ w2^T + b2
    {
        dim3 grid(H1 / 64, M2 / 128);    // (8, 1024)
        gemm2_s8_kernel<<<grid, 256, G2_SMEM>>>(spk, q2, b2, cur2);
    }

    // 5) fused LIF2 + output head
    fuse_out_kernel<<<BB, H1>>>(cur2, w3, b3, out);
}

// round 6
// speedup vs baseline: 1.3947x; 1.3572x over previous
#include <cuda_runtime.h>
#include <cstdint>
#include <cstddef>

// ---------------------------------------------------------------------------
// SNN forward:
//   cur1 = data @ w1^T + b1      -- fp32 SIMT GEMM (round-1 verbatim numerics)
//   pack[b,i] = 8 spike bits     -- elementwise LIF1 (beta1 = 1.0)
//   tail kernel (per batch row b):
//       ~59% of pattern bytes are 0 -> compact active list;
//       cur2[b,:,t] accumulated in registers via fma.rn.f32x2 + {0,1} LUT;
//       LIF2 + dot(w3) + mean fused in-register -> out[b]
//   (legacy mma.sync tensor path measured at only ~145 TOPS on sm_103a;
//    sparse fp32 beats it ~2.5x while cutting 512MB of cur2 traffic)
// ---------------------------------------------------------------------------

static constexpr int BB  = 16384;
static constexpr int DIN = 512;
static constexpr int H0  = 1024;
static constexpr int H1  = 512;
static constexpr int T   = 8;

// Scratch (device globals -- no runtime allocation allowed)
__device__ __align__(256) unsigned char g_pack[(size_t)BB * H0];  // 16 MB
__device__ __align__(256) float         g_w2t [(size_t)H0 * H1]; //  2 MB
__device__ __align__(256) float         g_cur1[(size_t)BB * H0]; // 64 MB

// ===========================================================================
// GEMM1: round-1 fp32 SIMT SGEMM (verbatim -- known-good numerics).
// C[m,n] = sum_k A[m,k] * W[n,k] + bias[n].  Tile 128x128x16, 8x8 micro.
// ===========================================================================
__global__ void __launch_bounds__(256) sgemm1_kernel(
    const float* __restrict__ A,
    const float* __restrict__ W,
    const float* __restrict__ bias,
    float* __restrict__ C,
    int M, int N, int K)
{
    __shared__ float As[16][128];
    __shared__ float Bs[16][128];

    const int tx = threadIdx.x;
    const int tm = tx >> 4;
    const int tn = tx & 15;

    const int m0 = blockIdx.y * 128;
    const int n0 = blockIdx.x * 128;

    float acc[8][8];
#pragma unroll
    for (int i = 0; i < 8; ++i)
#pragma unroll
        for (int j = 0; j < 8; ++j) acc[i][j] = 0.0f;

    for (int kt = 0; kt < K; kt += 16) {
#pragma unroll
        for (int s = 0; s < 2; ++s) {
            const int f  = tx + s * 256;
            const int r  = f >> 2;
            const int c4 = (f & 3) * 4;
            const int gk = kt + c4;
            {
                const int gm = m0 + r;
                float4 v = *reinterpret_cast<const float4*>(&A[(size_t)gm * K + gk]);
                As[c4 + 0][r] = v.x;
                As[c4 + 1][r] = v.y;
                As[c4 + 2][r] = v.z;
                As[c4 + 3][r] = v.w;
            }
            {
                const int gn = n0 + r;
                const float4 w = *reinterpret_cast<const float4*>(&W[(size_t)gn * K + gk]);
                Bs[c4 + 0][r] = w.x;
                Bs[c4 + 1][r] = w.y;
                Bs[c4 + 2][r] = w.z;
                Bs[c4 + 3][r] = w.w;
            }
        }
        __syncthreads();

#pragma unroll
        for (int k = 0; k < 16; ++k) {
            float a[8], b[8];
            *reinterpret_cast<float4*>(&a[0]) =
                *reinterpret_cast<const float4*>(&As[k][tm * 8]);
            *reinterpret_cast<float4*>(&a[4]) =
                *reinterpret_cast<const float4*>(&As[k][tm * 8 + 4]);
            *reinterpret_cast<float4*>(&b[0]) =
                *reinterpret_cast<const float4*>(&Bs[k][tn * 8]);
            *reinterpret_cast<float4*>(&b[4]) =
                *reinterpret_cast<const float4*>(&Bs[k][tn * 8 + 4]);
#pragma unroll
            for (int i = 0; i < 8; ++i)
#pragma unroll
                for (int j = 0; j < 8; ++j)
                    acc[i][j] = fmaf(a[i], b[j], acc[i][j]);
        }
        __syncthreads();
    }

    float bj[8];
    const int gn0 = n0 + tn * 8;
#pragma unroll
    for (int j = 0; j < 8; ++j) bj[j] = __ldg(&bias[gn0 + j]);

#pragma unroll
    for (int i = 0; i < 8; ++i) {
        const int gm = m0 + tm * 8 + i;
        float4 o0, o1;
        o0.x = acc[i][0] + bj[0];
        o0.y = acc[i][1] + bj[1];
        o0.z = acc[i][2] + bj[2];
        o0.w = acc[i][3] + bj[3];
        o1.x = acc[i][4] + bj[4];
        o1.y = acc[i][5] + bj[5];
        o1.z = acc[i][6] + bj[6];
        o1.w = acc[i][7] + bj[7];
        *reinterpret_cast<float4*>(&C[(size_t)gm * N + gn0])     = o0;
        *reinterpret_cast<float4*>(&C[(size_t)gm * N + gn0 + 4]) = o1;
    }
}

// ===========================================================================
// LIF layer 1 (beta1 = 1.0): 8 spike bits packed into one byte per (b,i)
// ===========================================================================
__global__ void spike_pack_kernel(const float* __restrict__ cur1,
                                  unsigned char* __restrict__ pack)
{
    const size_t i = (size_t)blockIdx.x * blockDim.x + threadIdx.x;
    if (i >= (size_t)BB * H0) return;
    const float c = cur1[i];
    float mem = 0.0f;
    unsigned p = 0;
#pragma unroll
    for (int t = 0; t < T; ++t) {
        const float reset = (mem > 1.0f) ? 1.0f : 0.0f;   // OLD mem
        mem = mem + c - reset;                             // beta1 = 1.0
        p |= ((mem - 1.0f) > 0.0f ? 1u : 0u) << t;
    }
    pack[i] = (unsigned char)p;
}

// ===========================================================================
// Transpose w2 [H1][H0] -> w2t [H0][H1]  (standard 32x32 smem tile)
// ===========================================================================
__global__ void transpose_w2_kernel(const float* __restrict__ w2,
                                    float* __restrict__ w2t)
{
    __shared__ float tile[32][33];
    const int bx = blockIdx.x * 32;   // i base
    const int by = blockIdx.y * 32;   // n base
    const int tx = threadIdx.x, ty = threadIdx.y;
#pragma unroll
    for (int j = 0; j < 32; j += 8)
        tile[ty + j][tx] = w2[(size_t)(by + ty + j) * H0 + bx + tx];
    __syncthreads();
#pragma unroll
    for (int j = 0; j < 32; j += 8)
        w2t[(size_t)(bx + ty + j) * H1 + by + tx] = tile[tx][ty + j];
}

// ===========================================================================
// Fused tail: per batch row b --
//   1) compact nonzero pattern bytes into an ordered smem list
//   2) for each active i: acc[t] += lut[p][t] * w2t[i]  (fma.rn.f32x2,
//      thread owns 2 adjacent n, 8 t accumulators)
//   3) LIF2 recurrence + spk2 . w3 in-register, block-reduce -> out[b]
// ===========================================================================
__global__ void __launch_bounds__(256) snn_tail_kernel(
    const unsigned char* __restrict__ pack,   // [BB][H0]
    const float* __restrict__ w2t,            // [H0][H1]
    const float* __restrict__ b2,
    const float* __restrict__ w3,
    const float* __restrict__ b3,
    float* __restrict__ out)
{
    __shared__ uint32_t s_list[H0];
    __shared__ unsigned long long s_lut[256][T];
    __shared__ int   s_warp[8];
    __shared__ int   s_len;
    __shared__ float s_red[8];

    const int b    = blockIdx.x;
    const int tid  = threadIdx.x;
    const int lane = tid & 31;
    const int wid  = tid >> 5;

    // ---- build {0,1} float-pair LUT: thread tid owns pattern tid ----
#pragma unroll
    for (int t = 0; t < T; ++t) {
        const float v = ((tid >> t) & 1) ? 1.0f : 0.0f;
        float2 f2; f2.x = v; f2.y = v;
        s_lut[tid][t] = *reinterpret_cast<unsigned long long*>(&f2);
    }

    // ---- compact nonzero pattern bytes (deterministic, ascending i) ----
    const uint32_t word =
        reinterpret_cast<const uint32_t*>(pack)[(size_t)b * (H0 / 4) + tid];
    uint32_t bytes[4];
    int cnt = 0;
#pragma unroll
    for (int j = 0; j < 4; ++j) {
        bytes[j] = (word >> (8 * j)) & 255u;
        cnt += (bytes[j] != 0u);
    }
    int pre = cnt;
#pragma unroll
    for (int d = 1; d < 32; d <<= 1) {
        const int v = __shfl_up_sync(0xFFFFFFFFu, pre, d);
        if (lane >= d) pre += v;
    }
    const int wtot = __shfl_sync(0xFFFFFFFFu, pre, 31);
    const int excl = pre - cnt;
    if (lane == 31) s_warp[wid] = wtot;
    __syncthreads();
    if (tid == 0) {
        int s = 0;
#pragma unroll
        for (int k = 0; k < 8; ++k) { const int v = s_warp[k]; s_warp[k] = s; s += v; }
        s_len = s;
    }
    __syncthreads();
    int pos = s_warp[wid] + excl;
#pragma unroll
    for (int j = 0; j < 4; ++j) {
        if (bytes[j]) s_list[pos++] = ((uint32_t)(tid * 4 + j) << 8) | bytes[j];
    }
    __syncthreads();
    const int len = s_len;

    // ---- sparse accumulate: 8 x f32x2 accumulators (2 n's x 8 t) ----
    unsigned long long acc[T];
#pragma unroll
    for (int t = 0; t < T; ++t) acc[t] = 0ull;   // (+0.0f, +0.0f)

    const unsigned long long* __restrict__ w2t64 =
        reinterpret_cast<const unsigned long long*>(w2t);

    for (int k = 0; k < len; ++k) {
        const uint32_t e = s_list[k];
        const uint32_t p = e & 255u;
        const uint32_t i = e >> 8;
        const unsigned long long w64 =
            __ldg(w2t64 + (size_t)i * (H1 / 2) + tid);
        const unsigned long long* lrow = s_lut[p];
#pragma unroll
        for (int t = 0; t < T; ++t)
            asm("fma.rn.f32x2 %0, %1, %2, %0;"
                : "+l"(acc[t]) : "l"(lrow[t]), "l"(w64));
    }

    // ---- LIF2 + output head (thread owns n0, n0+1) ----
    const int n0 = tid * 2;
    const float2 b2v = *reinterpret_cast<const float2*>(b2 + n0);
    const float2 w3v = *reinterpret_cast<const float2*>(w3 + n0);
    float mem0 = 0.0f, mem1 = 0.0f, aout = 0.0f;
#pragma unroll
    for (int t = 0; t < T; ++t) {
        const float2 a = *reinterpret_cast<float2*>(&acc[t]);
        const float c0 = a.x + b2v.x;
        const float c1 = a.y + b2v.y;
        const float r0 = (mem0 > 1.0f) ? 1.0f : 0.0f;   // reset on OLD mem
        const float r1 = (mem1 > 1.0f) ? 1.0f : 0.0f;
        mem0 = 0.95f * mem0 + c0 - r0;
        mem1 = 0.95f * mem1 + c1 - r1;
        aout += ((mem0 - 1.0f) > 0.0f) ? w3v.x : 0.0f;
        aout += ((mem1 - 1.0f) > 0.0f) ? w3v.y : 0.0f;
    }

    // block reduce
#pragma unroll
    for (int d = 16; d > 0; d >>= 1)
        aout += __shfl_down_sync(0xFFFFFFFFu, aout, d);
    if (lane == 0) s_red[wid] = aout;
    __syncthreads();
    if (tid == 0) {
        float s = 0.0f;
#pragma unroll
        for (int k = 0; k < 8; ++k) s += s_red[k];
        out[b] = s * (1.0f / T) + __ldg(&b3[0]);
    }
}

// ---------------------------------------------------------------------------
extern "C" void kernel_launch(void* const* d_in, const int* in_sizes, int n_in,
                              void* d_out, int out_size)
{
    const float* data = (const float*)d_in[0];
    const float* w1   = (const float*)d_in[1];
    const float* b1   = (const float*)d_in[2];
    const float* w2   = (const float*)d_in[3];
    const float* b2   = (const float*)d_in[4];
    const float* w3   = (const float*)d_in[5];
    const float* b3   = (const float*)d_in[6];
    float* out = (float*)d_out;

    unsigned char* pack;
    float *w2t, *cur1;
    cudaGetSymbolAddress((void**)&pack, g_pack);
    cudaGetSymbolAddress((void**)&w2t,  g_w2t);
    cudaGetSymbolAddress((void**)&cur1, g_cur1);

    // 1) GEMM1 (fp32 SIMT): cur1 = data @ w1^T + b1
    {
        dim3 grid(H0 / 128, BB / 128);   // (8, 128)
        sgemm1_kernel<<<grid, 256>>>(data, w1, b1, cur1, BB, H0, DIN);
    }

    // 2) transpose w2 -> w2t [H0][H1]
    {
        dim3 grid(H0 / 32, H1 / 32);     // (32, 16)
        transpose_w2_kernel<<<grid, dim3(32, 8)>>>(w2, w2t);
    }

    // 3) LIF1 spikes -> packed bytes
    {
        const size_t n = (size_t)BB * H0;
        spike_pack_kernel<<<(unsigned)((n + 255) / 256), 256>>>(cur1, pack);
    }

    // 4) fused sparse layer-2 + LIF2 + output head
    snn_tail_kernel<<<BB, 256>>>(pack, w2t, b2, w3, b3, out);
}